// round 1
// baseline (speedup 1.0000x reference)
#include <cuda_runtime.h>
#include <cstdint>

// Problem constants (fixed by the reference)
#define BB 2
#define LL 1024
#define MM 8
#define NN 16
#define CC 16
#define HH 64
#define WW 64
#define VOTES (MM * NN)          // 128
#define SLAB  (CC * HH * WW)     // 65536 floats = 256 KB per (b,l)

__global__ __launch_bounds__(256, 8)
void ht_vote_kernel(const float* __restrict__ feats,   // [B,L,N,C]
                    const int*   __restrict__ vsrc,    // [B,L,2]
                    const int*   __restrict__ vdst,    // [B,L,2]
                    const int*   __restrict__ isrc,    // [B,L,M]
                    const int*   __restrict__ idst,    // [B,L,N]
                    float* __restrict__ out)           // [B,L,C,H,W]
{
    __shared__ int   sbin[VOTES];
    __shared__ float sw[VOTES][CC];

    const int bl = blockIdx.x;        // (b*L + l)
    const int b  = bl >> 10;          // L == 1024
    const int t  = threadIdx.x;

    float* slab = out + (size_t)bl * SLAB;

    // ---- Phase Z: stream-zero this (b,l)'s 256 KB slab ----
    // 16384 float4 stores / 256 threads = 64 per thread, fully coalesced,
    // all independent -> deep store MLP, DRAM-bound.
    {
        float4* slab4 = (float4*)slab;
        const float4 z = make_float4(0.f, 0.f, 0.f, 0.f);
#pragma unroll
        for (int i = 0; i < 64; i++) {
            slab4[t + i * 256] = z;
        }
    }

    // ---- Phase A: compute the 128 votes into smem ----
    if (t < VOTES) {
        const int m = t >> 4;         // N == 16
        const int n = t & 15;

        const int s  = isrc[bl * MM + m];                 // broadcast across 16 threads
        const int d  = idst[(b * LL + s) * NN + n];       // coalesced 64B
        const int sy = vsrc[(b * LL + s) * 2 + 0];
        const int sx = vsrc[(b * LL + s) * 2 + 1];
        const int dy = vdst[(b * LL + d) * 2 + 0];
        const int dx = vdst[(b * LL + d) * 2 + 1];

        // voxels are int32; floor(float(dy) - float(sy)) == dy - sy exactly
        const int by = dy - sy + HH / 2;
        const int bx = dx - sx + WW / 2;
        const bool valid = (by >= 0) & (by < HH) & (bx >= 0) & (bx < WW);
        sbin[t] = valid ? (by * WW + bx) : -1;

        // 16 fp32 weights: contiguous 64B per thread; 16 threads (same s)
        // span a contiguous 1 KB of feats -> coalesced.
        const float4* f4 = (const float4*)(feats + (((size_t)(b * LL + s)) * NN + n) * CC);
        float4* w4 = (float4*)&sw[t][0];
#pragma unroll
        for (int k = 0; k < 4; k++) w4[k] = f4[k];
    }

    __syncthreads();   // orders Phase-Z stores before Phase-S atomics (block-private slab)

    // ---- Phase S: scatter 128 votes x 16 channels = 2048 atomicAdds ----
    // item i -> vote v = i/16, channel c = i%16. Conflicts only within this
    // CTA's own 128 votes (rare: ~2 duplicate bins expected), so atomics are
    // correct and cheap (lower to REDG).
#pragma unroll
    for (int k = 0; k < 8; k++) {
        const int i   = t + k * 256;
        const int v   = i >> 4;
        const int c   = i & 15;
        const int bin = sbin[v];
        if (bin >= 0) {
            atomicAdd(slab + c * (HH * WW) + bin, sw[v][c]);
        }
    }
}

extern "C" void kernel_launch(void* const* d_in, const int* in_sizes, int n_in,
                              void* d_out, int out_size)
{
    const float* feats = (const float*)d_in[0];   // [B,L,N,C] f32
    const int*   vsrc  = (const int*)  d_in[1];   // [B,L,2]   i32
    const int*   vdst  = (const int*)  d_in[2];   // [B,L,2]   i32
    const int*   isrc  = (const int*)  d_in[3];   // [B,L,M]   i32
    const int*   idst  = (const int*)  d_in[4];   // [B,L,N]   i32
    float*       out   = (float*)d_out;           // [B,L,C,H,W] f32

    ht_vote_kernel<<<BB * LL, 256>>>(feats, vsrc, vdst, isrc, idst, out);
}

// round 2
// speedup vs baseline: 1.3035x; 1.3035x over previous
#include <cuda_runtime.h>
#include <cstdint>

// Problem constants (fixed by the reference)
#define BB 2
#define LL 1024
#define MM 8
#define NN 16
#define CC 16
#define HH 64
#define WW 64
#define VOTES (MM * NN)            // 128
#define SLAB  (CC * HH * WW)       // 65536 floats = 256 KB per (b,l)
#define CGRP  4                    // channels per quantum
#define NGRP  (CC / CGRP)          // 4 quanta per slab
#define QFLOATS (CGRP * HH * WW)   // 16384 floats = 64 KB per quantum

// One CTA = one quantum = (slab bl, channel-group g).
// 8192 quanta over ~1184 concurrent CTA slots -> 6.92 quanta/slot,
// quantization loss ~1.2% (vs 16% with whole-slab quanta in R1).
__global__ __launch_bounds__(256, 8)
void ht_vote_kernel(const float* __restrict__ feats,   // [B,L,N,C]
                    const int*   __restrict__ vsrc,    // [B,L,2]
                    const int*   __restrict__ vdst,    // [B,L,2]
                    const int*   __restrict__ isrc,    // [B,L,M]
                    const int*   __restrict__ idst,    // [B,L,N]
                    float* __restrict__ out)           // [B,L,C,H,W]
{
    __shared__ int    sbin[VOTES];
    __shared__ float4 sw[VOTES];       // this quantum's 4 channels per vote

    const int q  = blockIdx.x;         // 0 .. B*L*NGRP-1
    const int bl = q >> 2;             // NGRP == 4
    const int g  = q & 3;              // channel group
    const int b  = bl >> 10;           // LL == 1024
    const int t  = threadIdx.x;

    // ---- Phase A (issue): gather chain, started BEFORE the store stream so
    // its ~3 dependent memory latencies hide under the stores. All index /
    // voxel data is tiny and L2-resident (shared by the 4 sibling CTAs).
    int    bin = -1;
    float4 w   = make_float4(0.f, 0.f, 0.f, 0.f);
    if (t < VOTES) {
        const int m = t >> 4;          // NN == 16
        const int n = t & 15;

        const int s  = isrc[bl * MM + m];
        const int d  = idst[(b * LL + s) * NN + n];
        const int sy = vsrc[(b * LL + s) * 2 + 0];
        const int sx = vsrc[(b * LL + s) * 2 + 1];
        const int dy = vdst[(b * LL + d) * 2 + 0];
        const int dx = vdst[(b * LL + d) * 2 + 1];

        // voxels are int32: floor(float sub) == integer sub exactly
        const int by = dy - sy + HH / 2;
        const int bx = dx - sx + WW / 2;
        if (((unsigned)by < HH) & ((unsigned)bx < WW)) bin = by * WW + bx;

        // 4 channels of this vote's weight vector (16B, coalesced)
        w = ((const float4*)(feats + (((size_t)(b * LL + s)) * NN + n) * CC))[g];
    }

    float* base = out + (size_t)bl * SLAB + g * QFLOATS;

    // ---- Phase Z: stream-zero this quantum's 64 KB ----
    {
        float4* b4 = (float4*)base;
        const float4 z = make_float4(0.f, 0.f, 0.f, 0.f);
#pragma unroll
        for (int i = 0; i < QFLOATS / 4 / 256; i++) {   // 16 per thread
            b4[t + i * 256] = z;
        }
    }

    // ---- Phase A (commit): publish votes to smem ----
    if (t < VOTES) {
        sbin[t] = bin;
        sw[t]   = w;
    }

    __syncthreads();   // orders Phase-Z stores before Phase-S atomics
                       // (quantum region is CTA-private)

    // ---- Phase S: 128 votes x 4 channels = 512 atomicAdds (2/thread) ----
#pragma unroll
    for (int k = 0; k < 2; k++) {
        const int i   = t + k * 256;   // 0..511
        const int v   = i >> 2;        // vote
        const int c   = i & 3;         // channel within group
        const int bn  = sbin[v];
        if (bn >= 0) {
            atomicAdd(base + c * (HH * WW) + bn, ((const float*)&sw[v])[c]);
        }
    }
}

extern "C" void kernel_launch(void* const* d_in, const int* in_sizes, int n_in,
                              void* d_out, int out_size)
{
    const float* feats = (const float*)d_in[0];   // [B,L,N,C] f32
    const int*   vsrc  = (const int*)  d_in[1];   // [B,L,2]   i32
    const int*   vdst  = (const int*)  d_in[2];   // [B,L,2]   i32
    const int*   isrc  = (const int*)  d_in[3];   // [B,L,M]   i32
    const int*   idst  = (const int*)  d_in[4];   // [B,L,N]   i32
    float*       out   = (float*)d_out;           // [B,L,C,H,W] f32

    ht_vote_kernel<<<BB * LL * NGRP, 256>>>(feats, vsrc, vdst, isrc, idst, out);
}